// round 8
// baseline (speedup 1.0000x reference)
#include <cuda_runtime.h>
#include <cstdint>

#define FULLM 0xffffffffu

constexpr int Bsz  = 16384;
constexpr int Sdim = 24;
constexpr int Adim = 4;
constexpr int Tlen = 40;

// ---- shared memory layout (float offsets); every table has a ZERO pad column ----
// wsain4 : float4 [57][32]  k<48: (Wsin[l][k], Wsin[l+32][k], 0, 0)
//                           48<=k<56: (0, 0, Wain[l][k-48], Wain[l+32][k-48]); k=56: zeros
// wsrec4 : float4 [65][32]  (Wsrec[l][k], Wsrec[l+32][k], Wro[k], 0); k=64: zeros
// warc1  : float4 [65][32]  (Warec[l][k], Warec[l+32][k], Wcin[l][k], Wcin[l+32][k]); k=64: zeros
// wc2r   : float2 [65][32]  (Wcin[l][64+k]+Wcrec[l][k], same l+32); k=64: zeros
#define OFF_WSAIN  0
#define OFF_WSREC4 7296
#define OFF_WARC1  15616
#define OFF_WC2R   23936
#define SMEM_FLOATS 28096

#define PAD_IN  56
#define PAD_Z   64

__device__ unsigned g_ticket;

__global__ void reset_ticket_kernel(unsigned start) { g_ticket = start; }

// extract next lowest set bit (ascending), or pad index if mask empty
__device__ __forceinline__ int next_k(unsigned long long& m, int pad) {
    int f = __ffsll((long long)m);
    int k = f ? (f - 1) : pad;
    m &= (m - 1);                 // 0 stays 0
    return k;
}

__global__ void __launch_bounds__(512, 2)
snn_kernel(const float* __restrict__ state, const float* __restrict__ action,
           const float* __restrict__ Wsin, const float* __restrict__ Wsrec,
           const float* __restrict__ Wain, const float* __restrict__ Warec,
           const float* __restrict__ Wcin, const float* __restrict__ Wcrec,
           const float* __restrict__ Wro, float* __restrict__ out)
{
    extern __shared__ float smem[];
    const int tid = threadIdx.x;

    // ---- cooperative weight load / transpose (exact fp32), zero pad columns ----
    for (int idx = tid; idx < 57 * 32; idx += 512) {
        int k = idx >> 5, l = idx & 31;
        float4 w4 = {0.f, 0.f, 0.f, 0.f};
        if (k < 48)      { w4.x = Wsin[l * 48 + k]; w4.y = Wsin[(l + 32) * 48 + k]; }
        else if (k < 56) { w4.z = Wain[l * 8 + (k - 48)]; w4.w = Wain[(l + 32) * 8 + (k - 48)]; }
        reinterpret_cast<float4*>(smem + OFF_WSAIN)[k * 32 + l] = w4;
    }
    for (int idx = tid; idx < 65 * 32; idx += 512) {
        int k = idx >> 5, l = idx & 31;
        float4 s4 = {0.f, 0.f, 0.f, 0.f};
        float4 w4 = {0.f, 0.f, 0.f, 0.f};
        float2 c2 = {0.f, 0.f};
        if (k < 64) {
            s4.x = Wsrec[l * 64 + k];  s4.y = Wsrec[(l + 32) * 64 + k];  s4.z = Wro[k];
            w4.x = Warec[l * 64 + k];  w4.y = Warec[(l + 32) * 64 + k];
            w4.z = Wcin[l * 128 + k];  w4.w = Wcin[(l + 32) * 128 + k];
            c2.x = __fadd_rn(Wcin[l * 128 + 64 + k],        Wcrec[l * 64 + k]);
            c2.y = __fadd_rn(Wcin[(l + 32) * 128 + 64 + k], Wcrec[(l + 32) * 64 + k]);
        }
        reinterpret_cast<float4*>(smem + OFF_WSREC4)[k * 32 + l] = s4;
        reinterpret_cast<float4*>(smem + OFF_WARC1)[k * 32 + l] = w4;
        reinterpret_cast<float2*>(smem + OFF_WC2R)[k * 32 + l]  = c2;
    }
    __syncthreads();

    const int lane = tid & 31;
    const float4* wsain  = reinterpret_cast<const float4*>(smem + OFF_WSAIN)  + lane;
    const float4* wsrec4 = reinterpret_cast<const float4*>(smem + OFF_WSREC4) + lane;
    const float4* warc1  = reinterpret_cast<const float4*>(smem + OFF_WARC1)  + lane;
    const float2* wc2r   = reinterpret_cast<const float2*>(smem + OFF_WC2R)   + lane;

    unsigned b = blockIdx.x * 16u + (unsigned)(tid >> 5);

    while (b < (unsigned)Bsz) {
        const float* srow = state  + (size_t)b * Sdim;
        const float* arow = action + (size_t)b * Adim;

        float c0, c1;
        if (lane < 24) c0 = fmaxf(__fmul_rn(50.f, srow[lane]), 0.f);
        else           c0 = fmaxf(__fmul_rn(-50.f, srow[lane - 24]), 0.f);
        if (lane < 16)      c1 = fmaxf(__fmul_rn(-50.f, srow[8 + lane]), 0.f);
        else if (lane < 20) c1 = fmaxf(__fmul_rn(50.f, arow[lane - 16]), 0.f);
        else if (lane < 24) c1 = fmaxf(__fmul_rn(-50.f, arow[lane - 20]), 0.f);
        else                c1 = 0.f;

        bool alw0 = __fmul_rn(0.1f, c0) > 1.0f;
        bool alw1 = (lane < 24) && (__fmul_rn(0.1f, c1) > 1.0f);
        unsigned alo = __ballot_sync(FULLM, alw0);
        unsigned ahi = __ballot_sync(FULLM, alw1);
        unsigned long long x_always = (unsigned long long)alo | ((unsigned long long)ahi << 32);

        // hoisted base sums over always-on inputs
        float bs0 = 0.f, bs1 = 0.f, ba0 = 0.f, ba1 = 0.f;
        {
            unsigned long long m = x_always;
            while (m) {
                int k = next_k(m, PAD_IN);
                float4 w = wsain[k * 32];
                bs0 += w.x; bs1 += w.y; ba0 += w.z; ba1 += w.w;
            }
        }

        float ve0 = 0.f, ve1 = 0.f;
        float v0 = 0.f, v1 = 0.f;
        float i0 = 0.f, i1 = 0.f;
        float r0 = 0.f, r1 = 0.f;
        float vli = 0.f, ili = 0.f;
        float vmax = -3.0e38f;

        for (int t = 0; t < Tlen; t++) {
            // ---- encoder ----
            ve0 = __fmaf_rn(0.1f, __fsub_rn(c0, ve0), ve0);
            bool s0 = __fsub_rn(ve0, 1.0f) > 0.0f; if (s0) ve0 = 0.f;
            ve1 = __fmaf_rn(0.1f, __fsub_rn(c1, ve1), ve1);
            bool s1 = (lane < 24) && (__fsub_rn(ve1, 1.0f) > 0.0f); if (s1) ve1 = 0.f;
            unsigned mlo = __ballot_sync(FULLM, s0);
            unsigned mhi = __ballot_sync(FULLM, s1);
            unsigned long long xall = (unsigned long long)mlo | ((unsigned long long)mhi << 32);

            // ---- lif1 ----
            float id0 = __fmaf_rn(-0.2f, i0, i0);
            float id1 = __fmaf_rn(-0.2f, i1, i1);
            float vd0 = __fmaf_rn(0.1f, __fsub_rn(i0, v0), v0);
            float vd1 = __fmaf_rn(0.1f, __fsub_rn(i1, v1), v1);
            bool zs0 = __fsub_rn(vd0, 1.0f) > 0.0f; v0 = zs0 ? 0.f : vd0;
            bool zs1 = __fsub_rn(vd1, 1.0f) > 0.0f; v1 = zs1 ? 0.f : vd1;

            // dev walk (small): group-of-2 batched loads
            float a0 = bs0, a1 = bs1, p0 = ba0, p1 = ba1;
            {
                unsigned long long m = xall & ~x_always;
                while (m) {
                    int k0 = next_k(m, PAD_IN);
                    int k1 = next_k(m, PAD_IN);
                    float4 w0 = wsain[k0 * 32];
                    float4 w1 = wsain[k1 * 32];
                    a0 = __fadd_rn(a0, __fadd_rn(w0.x, w1.x));
                    a1 = __fadd_rn(a1, __fadd_rn(w0.y, w1.y));
                    p0 = __fadd_rn(p0, __fadd_rn(w0.z, w1.z));
                    p1 = __fadd_rn(p1, __fadd_rn(w0.w, w1.w));
                }
            }
            i0 = __fadd_rn(__fadd_rn(id0, a0), r0);
            i1 = __fadd_rn(__fadd_rn(id1, a1), r1);

            unsigned zslo = __ballot_sync(FULLM, zs0);
            unsigned zshi = __ballot_sync(FULLM, zs1);
            unsigned long long zsm = (unsigned long long)zslo | ((unsigned long long)zshi << 32);

            // ---- lif2 (+ Wcin[:, :64]·z_s for lif3): group-of-4 batched walk ----
            id0 = __fmaf_rn(-0.2f, i0, i0);
            id1 = __fmaf_rn(-0.2f, i1, i1);
            vd0 = __fmaf_rn(0.1f, __fsub_rn(i0, v0), v0);
            vd1 = __fmaf_rn(0.1f, __fsub_rn(i1, v1), v1);
            bool za0 = __fsub_rn(vd0, 1.0f) > 0.0f; v0 = za0 ? 0.f : vd0;
            bool za1 = __fsub_rn(vd1, 1.0f) > 0.0f; v1 = za1 ? 0.f : vd1;

            float q0 = 0.f, q1 = 0.f, u0 = 0.f, u1 = 0.f;
            {
                unsigned long long m = zsm;
                while (m) {
                    int k0 = next_k(m, PAD_Z);
                    int k1 = next_k(m, PAD_Z);
                    int k2 = next_k(m, PAD_Z);
                    int k3 = next_k(m, PAD_Z);
                    float4 w0 = warc1[k0 * 32];
                    float4 w1 = warc1[k1 * 32];
                    float4 w2 = warc1[k2 * 32];
                    float4 w3 = warc1[k3 * 32];
                    q0 = __fadd_rn(q0, __fadd_rn(__fadd_rn(w0.x, w1.x), __fadd_rn(w2.x, w3.x)));
                    q1 = __fadd_rn(q1, __fadd_rn(__fadd_rn(w0.y, w1.y), __fadd_rn(w2.y, w3.y)));
                    u0 = __fadd_rn(u0, __fadd_rn(__fadd_rn(w0.z, w1.z), __fadd_rn(w2.z, w3.z)));
                    u1 = __fadd_rn(u1, __fadd_rn(__fadd_rn(w0.w, w1.w), __fadd_rn(w2.w, w3.w)));
                }
            }
            i0 = __fadd_rn(__fadd_rn(id0, p0), q0);
            i1 = __fadd_rn(__fadd_rn(id1, p1), q1);

            unsigned zalo = __ballot_sync(FULLM, za0);
            unsigned zahi = __ballot_sync(FULLM, za1);
            unsigned long long zam = (unsigned long long)zalo | ((unsigned long long)zahi << 32);

            // ---- lif3 (merged Wcin2+Wcrec): group-of-4 batched walk ----
            id0 = __fmaf_rn(-0.2f, i0, i0);
            id1 = __fmaf_rn(-0.2f, i1, i1);
            vd0 = __fmaf_rn(0.1f, __fsub_rn(i0, v0), v0);
            vd1 = __fmaf_rn(0.1f, __fsub_rn(i1, v1), v1);
            bool z0 = __fsub_rn(vd0, 1.0f) > 0.0f; v0 = z0 ? 0.f : vd0;
            bool z1 = __fsub_rn(vd1, 1.0f) > 0.0f; v1 = z1 ? 0.f : vd1;

            float e0 = u0, e1 = u1;
            {
                unsigned long long m = zam;
                while (m) {
                    int k0 = next_k(m, PAD_Z);
                    int k1 = next_k(m, PAD_Z);
                    int k2 = next_k(m, PAD_Z);
                    int k3 = next_k(m, PAD_Z);
                    float2 w0 = wc2r[k0 * 32];
                    float2 w1 = wc2r[k1 * 32];
                    float2 w2 = wc2r[k2 * 32];
                    float2 w3 = wc2r[k3 * 32];
                    e0 = __fadd_rn(e0, __fadd_rn(__fadd_rn(w0.x, w1.x), __fadd_rn(w2.x, w3.x)));
                    e1 = __fadd_rn(e1, __fadd_rn(__fadd_rn(w0.y, w1.y), __fadd_rn(w2.y, w3.y)));
                }
            }
            i0 = __fadd_rn(id0, e0);
            i1 = __fadd_rn(id1, e1);

            unsigned zlo = __ballot_sync(FULLM, z0);
            unsigned zhi = __ballot_sync(FULLM, z1);
            unsigned long long zm = (unsigned long long)zlo | ((unsigned long long)zhi << 32);

            // ---- combined recurrent+readout gather over fresh zm: group-of-4 ----
            float nr0 = 0.f, nr1 = 0.f, ro = 0.f;
            {
                unsigned long long m = zm;
                while (m) {
                    int k0 = next_k(m, PAD_Z);
                    int k1 = next_k(m, PAD_Z);
                    int k2 = next_k(m, PAD_Z);
                    int k3 = next_k(m, PAD_Z);
                    float4 w0 = wsrec4[k0 * 32];
                    float4 w1 = wsrec4[k1 * 32];
                    float4 w2 = wsrec4[k2 * 32];
                    float4 w3 = wsrec4[k3 * 32];
                    nr0 = __fadd_rn(nr0, __fadd_rn(__fadd_rn(w0.x, w1.x), __fadd_rn(w2.x, w3.x)));
                    nr1 = __fadd_rn(nr1, __fadd_rn(__fadd_rn(w0.y, w1.y), __fadd_rn(w2.y, w3.y)));
                    ro  = __fadd_rn(ro,  __fadd_rn(__fadd_rn(w0.z, w1.z), __fadd_rn(w2.z, w3.z)));
                }
            }
            r0 = nr0; r1 = nr1;

            // ---- LI readout ----
            vli = __fmaf_rn(0.1f, __fsub_rn(ili, vli), vli);
            ili = __fadd_rn(__fmaf_rn(-0.2f, ili, ili), ro);
            vmax = fmaxf(vmax, vli);
        }

        if (lane == 0) out[b] = vmax;

        if (lane == 0) b = atomicAdd(&g_ticket, 1u);
        b = __shfl_sync(FULLM, b, 0);
    }
}

extern "C" void kernel_launch(void* const* d_in, const int* in_sizes, int n_in,
                              void* d_out, int out_size)
{
    const float* state  = (const float*)d_in[0];
    const float* action = (const float*)d_in[1];
    const float* Wsin   = (const float*)d_in[2];
    const float* Wsrec  = (const float*)d_in[3];
    const float* Wain   = (const float*)d_in[4];
    const float* Warec  = (const float*)d_in[5];
    const float* Wcin   = (const float*)d_in[6];
    const float* Wcrec  = (const float*)d_in[7];
    const float* Wro    = (const float*)d_in[8];

    int sms = 148;
    cudaDeviceGetAttribute(&sms, cudaDevAttrMultiProcessorCount, 0);
    int grid = sms * 2;
    unsigned nwarps = (unsigned)grid * 16u;

    cudaFuncSetAttribute(snn_kernel, cudaFuncAttributeMaxDynamicSharedMemorySize,
                         SMEM_FLOATS * sizeof(float));

    reset_ticket_kernel<<<1, 1>>>(nwarps);
    snn_kernel<<<grid, 512, SMEM_FLOATS * sizeof(float)>>>(
        state, action, Wsin, Wsrec, Wain, Warec, Wcin, Wcrec, Wro, (float*)d_out);
}

// round 9
// speedup vs baseline: 1.7977x; 1.7977x over previous
#include <cuda_runtime.h>
#include <cstdint>

#define FULLM 0xffffffffu

constexpr int Bsz  = 16384;
constexpr int Sdim = 24;
constexpr int Adim = 4;
constexpr int Tlen = 40;

// ---- shared memory layout (float offsets) ----
// wsain4 : float4 [56][32]  k<48: (Wsin[l][k], Wsin[l+32][k], 0, 0)
//                           k>=48:(0, 0, Wain[l][k-48], Wain[l+32][k-48])
// wsrec4 : float4 [64][32]  (Wsrec[l][k], Wsrec[l+32][k], Wro[k], 0)
// warc1  : float4 [64][32]  (Warec[l][k], Warec[l+32][k], Wcin[l][k], Wcin[l+32][k])
// wc2r   : float2 [64][32]  (Wcin[l][64+k]+Wcrec[l][k], same for l+32) [merged]
#define OFF_WSAIN  0
#define OFF_WSREC4 7168
#define OFF_WARC1  15360
#define OFF_WC2R   23552
#define SMEM_FLOATS 27648

__device__ unsigned g_ticket;

__global__ void reset_ticket_kernel(unsigned start) { g_ticket = start; }

__global__ void __launch_bounds__(512, 2)
snn_kernel(const float* __restrict__ state, const float* __restrict__ action,
           const float* __restrict__ Wsin, const float* __restrict__ Wsrec,
           const float* __restrict__ Wain, const float* __restrict__ Warec,
           const float* __restrict__ Wcin, const float* __restrict__ Wcrec,
           const float* __restrict__ Wro, float* __restrict__ out)
{
    extern __shared__ float smem[];
    const int tid = threadIdx.x;

    // ---- cooperative weight load / transpose (exact fp32) ----
    for (int idx = tid; idx < 56 * 32; idx += 512) {
        int k = idx >> 5, l = idx & 31;
        float4 w4 = {0.f, 0.f, 0.f, 0.f};
        if (k < 48) { w4.x = Wsin[l * 48 + k]; w4.y = Wsin[(l + 32) * 48 + k]; }
        else        { w4.z = Wain[l * 8 + (k - 48)]; w4.w = Wain[(l + 32) * 8 + (k - 48)]; }
        reinterpret_cast<float4*>(smem + OFF_WSAIN)[k * 32 + l] = w4;
    }
    for (int idx = tid; idx < 64 * 32; idx += 512) {
        int k = idx >> 5, l = idx & 31;
        float4 s4;
        s4.x = Wsrec[l * 64 + k];
        s4.y = Wsrec[(l + 32) * 64 + k];
        s4.z = Wro[k];
        s4.w = 0.f;
        reinterpret_cast<float4*>(smem + OFF_WSREC4)[k * 32 + l] = s4;
        float4 w4;
        w4.x = Warec[l * 64 + k];
        w4.y = Warec[(l + 32) * 64 + k];
        w4.z = Wcin[l * 128 + k];
        w4.w = Wcin[(l + 32) * 128 + k];
        reinterpret_cast<float4*>(smem + OFF_WARC1)[k * 32 + l] = w4;
        smem[OFF_WC2R + k * 64 + 2 * l]     = __fadd_rn(Wcin[l * 128 + 64 + k],        Wcrec[l * 64 + k]);
        smem[OFF_WC2R + k * 64 + 2 * l + 1] = __fadd_rn(Wcin[(l + 32) * 128 + 64 + k], Wcrec[(l + 32) * 64 + k]);
    }
    __syncthreads();

    const int lane = tid & 31;
    const float4* wsain  = reinterpret_cast<const float4*>(smem + OFF_WSAIN)  + lane;
    const float4* wsrec4 = reinterpret_cast<const float4*>(smem + OFF_WSREC4) + lane;
    const float4* warc1  = reinterpret_cast<const float4*>(smem + OFF_WARC1)  + lane;
    const float2* wc2r   = reinterpret_cast<const float2*>(smem + OFF_WC2R)   + lane;

    unsigned b = blockIdx.x * 16u + (unsigned)(tid >> 5);

    while (b < (unsigned)Bsz) {
        const float* srow = state  + (size_t)b * Sdim;
        const float* arow = action + (size_t)b * Adim;

        float c0, c1;
        if (lane < 24) c0 = fmaxf(__fmul_rn(50.f, srow[lane]), 0.f);
        else           c0 = fmaxf(__fmul_rn(-50.f, srow[lane - 24]), 0.f);
        if (lane < 16)      c1 = fmaxf(__fmul_rn(-50.f, srow[8 + lane]), 0.f);
        else if (lane < 20) c1 = fmaxf(__fmul_rn(50.f, arow[lane - 16]), 0.f);
        else if (lane < 24) c1 = fmaxf(__fmul_rn(-50.f, arow[lane - 20]), 0.f);
        else                c1 = 0.f;

        bool alw0 = __fmul_rn(0.1f, c0) > 1.0f;
        bool alw1 = (lane < 24) && (__fmul_rn(0.1f, c1) > 1.0f);
        unsigned alo = __ballot_sync(FULLM, alw0);
        unsigned ahi = __ballot_sync(FULLM, alw1);
        unsigned long long x_always = (unsigned long long)alo | ((unsigned long long)ahi << 32);

        // hoisted base sums over always-on inputs (cold path, simple walk)
        float bs0 = 0.f, bs1 = 0.f, ba0 = 0.f, ba1 = 0.f;
        {
            unsigned m = (unsigned)x_always;
            while (m) { int k = __ffs(m) - 1; m &= m - 1;
                        float4 w = wsain[k * 32];
                        bs0 += w.x; bs1 += w.y; ba0 += w.z; ba1 += w.w; }
            m = (unsigned)(x_always >> 32);
            while (m) { int k = __ffs(m) - 1 + 32; m &= m - 1;
                        float4 w = wsain[k * 32];
                        bs0 += w.x; bs1 += w.y; ba0 += w.z; ba1 += w.w; }
        }

        float ve0 = 0.f, ve1 = 0.f;
        float v0 = 0.f, v1 = 0.f;
        float i0 = 0.f, i1 = 0.f;
        float r0 = 0.f, r1 = 0.f;
        float vli = 0.f, ili = 0.f;
        float vmax = -3.0e38f;

        for (int t = 0; t < Tlen; t++) {
            // ---- encoder ----
            ve0 = __fmaf_rn(0.1f, __fsub_rn(c0, ve0), ve0);
            bool s0 = __fsub_rn(ve0, 1.0f) > 0.0f; if (s0) ve0 = 0.f;
            ve1 = __fmaf_rn(0.1f, __fsub_rn(c1, ve1), ve1);
            bool s1 = (lane < 24) && (__fsub_rn(ve1, 1.0f) > 0.0f); if (s1) ve1 = 0.f;
            unsigned mlo = __ballot_sync(FULLM, s0);
            unsigned mhi = __ballot_sync(FULLM, s1);

            // ---- lif1 ----
            float id0 = __fmaf_rn(-0.2f, i0, i0);
            float id1 = __fmaf_rn(-0.2f, i1, i1);
            float vd0 = __fmaf_rn(0.1f, __fsub_rn(i0, v0), v0);
            float vd1 = __fmaf_rn(0.1f, __fsub_rn(i1, v1), v1);
            bool zs0 = __fsub_rn(vd0, 1.0f) > 0.0f; v0 = zs0 ? 0.f : vd0;
            bool zs1 = __fsub_rn(vd1, 1.0f) > 0.0f; v1 = zs1 ? 0.f : vd1;

            // dev walk: lo/hi chains interleaved (2 independent LDS streams)
            float a0 = bs0, a1 = bs1, p0 = ba0, p1 = ba1;
            float A0 = 0.f, A1 = 0.f, P0 = 0.f, P1 = 0.f;
            {
                unsigned ml = mlo & ~(unsigned)x_always;
                unsigned mh = mhi & ~(unsigned)(x_always >> 32);
                while (ml && mh) {
                    int k0 = __ffs(ml) - 1; ml &= ml - 1;
                    int k1 = __ffs(mh) - 1; mh &= mh - 1;
                    float4 w0 = wsain[k0 * 32];
                    float4 w1 = wsain[(k1 + 32) * 32];
                    a0 = __fadd_rn(a0, w0.x); a1 = __fadd_rn(a1, w0.y);
                    p0 = __fadd_rn(p0, w0.z); p1 = __fadd_rn(p1, w0.w);
                    A0 = __fadd_rn(A0, w1.x); A1 = __fadd_rn(A1, w1.y);
                    P0 = __fadd_rn(P0, w1.z); P1 = __fadd_rn(P1, w1.w);
                }
                while (ml) {
                    int k0 = __ffs(ml) - 1; ml &= ml - 1;
                    float4 w0 = wsain[k0 * 32];
                    a0 = __fadd_rn(a0, w0.x); a1 = __fadd_rn(a1, w0.y);
                    p0 = __fadd_rn(p0, w0.z); p1 = __fadd_rn(p1, w0.w);
                }
                while (mh) {
                    int k1 = __ffs(mh) - 1; mh &= mh - 1;
                    float4 w1 = wsain[(k1 + 32) * 32];
                    A0 = __fadd_rn(A0, w1.x); A1 = __fadd_rn(A1, w1.y);
                    P0 = __fadd_rn(P0, w1.z); P1 = __fadd_rn(P1, w1.w);
                }
            }
            a0 = __fadd_rn(a0, A0); a1 = __fadd_rn(a1, A1);
            p0 = __fadd_rn(p0, P0); p1 = __fadd_rn(p1, P1);
            i0 = __fadd_rn(__fadd_rn(id0, a0), r0);
            i1 = __fadd_rn(__fadd_rn(id1, a1), r1);

            unsigned zslo = __ballot_sync(FULLM, zs0);
            unsigned zshi = __ballot_sync(FULLM, zs1);

            // ---- lif2 (+ Wcin[:, :64]·z_s for lif3) ----
            id0 = __fmaf_rn(-0.2f, i0, i0);
            id1 = __fmaf_rn(-0.2f, i1, i1);
            vd0 = __fmaf_rn(0.1f, __fsub_rn(i0, v0), v0);
            vd1 = __fmaf_rn(0.1f, __fsub_rn(i1, v1), v1);
            bool za0 = __fsub_rn(vd0, 1.0f) > 0.0f; v0 = za0 ? 0.f : vd0;
            bool za1 = __fsub_rn(vd1, 1.0f) > 0.0f; v1 = za1 ? 0.f : vd1;

            float q0 = 0.f, q1 = 0.f, u0 = 0.f, u1 = 0.f;
            float Q0 = 0.f, Q1 = 0.f, U0 = 0.f, U1 = 0.f;
            {
                unsigned ml = zslo, mh = zshi;
                while (ml && mh) {
                    int k0 = __ffs(ml) - 1; ml &= ml - 1;
                    int k1 = __ffs(mh) - 1; mh &= mh - 1;
                    float4 w0 = warc1[k0 * 32];
                    float4 w1 = warc1[(k1 + 32) * 32];
                    q0 = __fadd_rn(q0, w0.x); q1 = __fadd_rn(q1, w0.y);
                    u0 = __fadd_rn(u0, w0.z); u1 = __fadd_rn(u1, w0.w);
                    Q0 = __fadd_rn(Q0, w1.x); Q1 = __fadd_rn(Q1, w1.y);
                    U0 = __fadd_rn(U0, w1.z); U1 = __fadd_rn(U1, w1.w);
                }
                while (ml) {
                    int k0 = __ffs(ml) - 1; ml &= ml - 1;
                    float4 w0 = warc1[k0 * 32];
                    q0 = __fadd_rn(q0, w0.x); q1 = __fadd_rn(q1, w0.y);
                    u0 = __fadd_rn(u0, w0.z); u1 = __fadd_rn(u1, w0.w);
                }
                while (mh) {
                    int k1 = __ffs(mh) - 1; mh &= mh - 1;
                    float4 w1 = warc1[(k1 + 32) * 32];
                    Q0 = __fadd_rn(Q0, w1.x); Q1 = __fadd_rn(Q1, w1.y);
                    U0 = __fadd_rn(U0, w1.z); U1 = __fadd_rn(U1, w1.w);
                }
            }
            q0 = __fadd_rn(q0, Q0); q1 = __fadd_rn(q1, Q1);
            u0 = __fadd_rn(u0, U0); u1 = __fadd_rn(u1, U1);
            i0 = __fadd_rn(__fadd_rn(id0, p0), q0);
            i1 = __fadd_rn(__fadd_rn(id1, p1), q1);

            unsigned zalo = __ballot_sync(FULLM, za0);
            unsigned zahi = __ballot_sync(FULLM, za1);

            // ---- lif3 (merged Wcin2+Wcrec on z_a) ----
            id0 = __fmaf_rn(-0.2f, i0, i0);
            id1 = __fmaf_rn(-0.2f, i1, i1);
            vd0 = __fmaf_rn(0.1f, __fsub_rn(i0, v0), v0);
            vd1 = __fmaf_rn(0.1f, __fsub_rn(i1, v1), v1);
            bool z0 = __fsub_rn(vd0, 1.0f) > 0.0f; v0 = z0 ? 0.f : vd0;
            bool z1 = __fsub_rn(vd1, 1.0f) > 0.0f; v1 = z1 ? 0.f : vd1;

            float e0 = u0, e1 = u1;
            float E0 = 0.f, E1 = 0.f;
            {
                unsigned ml = zalo, mh = zahi;
                while (ml && mh) {
                    int k0 = __ffs(ml) - 1; ml &= ml - 1;
                    int k1 = __ffs(mh) - 1; mh &= mh - 1;
                    float2 w0 = wc2r[k0 * 32];
                    float2 w1 = wc2r[(k1 + 32) * 32];
                    e0 = __fadd_rn(e0, w0.x); e1 = __fadd_rn(e1, w0.y);
                    E0 = __fadd_rn(E0, w1.x); E1 = __fadd_rn(E1, w1.y);
                }
                while (ml) {
                    int k0 = __ffs(ml) - 1; ml &= ml - 1;
                    float2 w0 = wc2r[k0 * 32];
                    e0 = __fadd_rn(e0, w0.x); e1 = __fadd_rn(e1, w0.y);
                }
                while (mh) {
                    int k1 = __ffs(mh) - 1; mh &= mh - 1;
                    float2 w1 = wc2r[(k1 + 32) * 32];
                    E0 = __fadd_rn(E0, w1.x); E1 = __fadd_rn(E1, w1.y);
                }
            }
            e0 = __fadd_rn(e0, E0); e1 = __fadd_rn(e1, E1);
            i0 = __fadd_rn(id0, e0);
            i1 = __fadd_rn(id1, e1);

            unsigned zlo = __ballot_sync(FULLM, z0);
            unsigned zhi = __ballot_sync(FULLM, z1);

            // ---- combined recurrent+readout gather over fresh zm ----
            float nr0 = 0.f, nr1 = 0.f, ro = 0.f;
            float NR0 = 0.f, NR1 = 0.f, RO = 0.f;
            {
                unsigned ml = zlo, mh = zhi;
                while (ml && mh) {
                    int k0 = __ffs(ml) - 1; ml &= ml - 1;
                    int k1 = __ffs(mh) - 1; mh &= mh - 1;
                    float4 w0 = wsrec4[k0 * 32];
                    float4 w1 = wsrec4[(k1 + 32) * 32];
                    nr0 = __fadd_rn(nr0, w0.x); nr1 = __fadd_rn(nr1, w0.y);
                    ro  = __fadd_rn(ro,  w0.z);
                    NR0 = __fadd_rn(NR0, w1.x); NR1 = __fadd_rn(NR1, w1.y);
                    RO  = __fadd_rn(RO,  w1.z);
                }
                while (ml) {
                    int k0 = __ffs(ml) - 1; ml &= ml - 1;
                    float4 w0 = wsrec4[k0 * 32];
                    nr0 = __fadd_rn(nr0, w0.x); nr1 = __fadd_rn(nr1, w0.y);
                    ro  = __fadd_rn(ro,  w0.z);
                }
                while (mh) {
                    int k1 = __ffs(mh) - 1; mh &= mh - 1;
                    float4 w1 = wsrec4[(k1 + 32) * 32];
                    NR0 = __fadd_rn(NR0, w1.x); NR1 = __fadd_rn(NR1, w1.y);
                    RO  = __fadd_rn(RO,  w1.z);
                }
            }
            r0 = __fadd_rn(nr0, NR0); r1 = __fadd_rn(nr1, NR1);
            ro = __fadd_rn(ro, RO);

            // ---- LI readout ----
            vli = __fmaf_rn(0.1f, __fsub_rn(ili, vli), vli);
            ili = __fadd_rn(__fmaf_rn(-0.2f, ili, ili), ro);
            vmax = fmaxf(vmax, vli);
        }

        if (lane == 0) out[b] = vmax;

        if (lane == 0) b = atomicAdd(&g_ticket, 1u);
        b = __shfl_sync(FULLM, b, 0);
    }
}

extern "C" void kernel_launch(void* const* d_in, const int* in_sizes, int n_in,
                              void* d_out, int out_size)
{
    const float* state  = (const float*)d_in[0];
    const float* action = (const float*)d_in[1];
    const float* Wsin   = (const float*)d_in[2];
    const float* Wsrec  = (const float*)d_in[3];
    const float* Wain   = (const float*)d_in[4];
    const float* Warec  = (const float*)d_in[5];
    const float* Wcin   = (const float*)d_in[6];
    const float* Wcrec  = (const float*)d_in[7];
    const float* Wro    = (const float*)d_in[8];

    int sms = 148;
    cudaDeviceGetAttribute(&sms, cudaDevAttrMultiProcessorCount, 0);
    int grid = sms * 2;
    unsigned nwarps = (unsigned)grid * 16u;

    cudaFuncSetAttribute(snn_kernel, cudaFuncAttributeMaxDynamicSharedMemorySize,
                         SMEM_FLOATS * sizeof(float));

    reset_ticket_kernel<<<1, 1>>>(nwarps);
    snn_kernel<<<grid, 512, SMEM_FLOATS * sizeof(float)>>>(
        state, action, Wsin, Wsrec, Wain, Warec, Wcin, Wcrec, Wro, (float*)d_out);
}

// round 10
// speedup vs baseline: 2.0022x; 1.1137x over previous
#include <cuda_runtime.h>
#include <cstdint>

#define FULLM 0xffffffffu

constexpr int Bsz  = 16384;
constexpr int Sdim = 24;
constexpr int Adim = 4;
constexpr int Tlen = 40;
constexpr int THREADS = 704;             // 22 warps/CTA, 2 CTAs/SM -> 44 warps/SM
constexpr int WPB = THREADS / 32;

// ---- shared memory layout (float offsets) ----
// wsain4 : float4 [56][32]  k<48: (Wsin[l][k], Wsin[l+32][k], 0, 0)
//                           k>=48:(0, 0, Wain[l][k-48], Wain[l+32][k-48])
// wsrec4 : float4 [64][32]  (Wsrec[l][k], Wsrec[l+32][k], Wro[k], 0)
// warc1  : float4 [64][32]  (Warec[l][k], Warec[l+32][k], Wcin[l][k], Wcin[l+32][k])
// wc2r   : float2 [64][32]  (Wcin[l][64+k]+Wcrec[l][k], same for l+32) [merged]
#define OFF_WSAIN  0
#define OFF_WSREC4 7168
#define OFF_WARC1  15360
#define OFF_WC2R   23552
#define SMEM_FLOATS 27648

__device__ unsigned g_ticket;

__global__ void reset_ticket_kernel(unsigned start) { g_ticket = start; }

__global__ void __launch_bounds__(THREADS, 2)
snn_kernel(const float* __restrict__ state, const float* __restrict__ action,
           const float* __restrict__ Wsin, const float* __restrict__ Wsrec,
           const float* __restrict__ Wain, const float* __restrict__ Warec,
           const float* __restrict__ Wcin, const float* __restrict__ Wcrec,
           const float* __restrict__ Wro, float* __restrict__ out)
{
    extern __shared__ float smem[];
    const int tid = threadIdx.x;

    // ---- cooperative weight load / transpose (exact fp32) ----
    for (int idx = tid; idx < 56 * 32; idx += THREADS) {
        int k = idx >> 5, l = idx & 31;
        float4 w4 = {0.f, 0.f, 0.f, 0.f};
        if (k < 48) { w4.x = Wsin[l * 48 + k]; w4.y = Wsin[(l + 32) * 48 + k]; }
        else        { w4.z = Wain[l * 8 + (k - 48)]; w4.w = Wain[(l + 32) * 8 + (k - 48)]; }
        reinterpret_cast<float4*>(smem + OFF_WSAIN)[k * 32 + l] = w4;
    }
    for (int idx = tid; idx < 64 * 32; idx += THREADS) {
        int k = idx >> 5, l = idx & 31;
        float4 s4;
        s4.x = Wsrec[l * 64 + k];
        s4.y = Wsrec[(l + 32) * 64 + k];
        s4.z = Wro[k];
        s4.w = 0.f;
        reinterpret_cast<float4*>(smem + OFF_WSREC4)[k * 32 + l] = s4;
        float4 w4;
        w4.x = Warec[l * 64 + k];
        w4.y = Warec[(l + 32) * 64 + k];
        w4.z = Wcin[l * 128 + k];
        w4.w = Wcin[(l + 32) * 128 + k];
        reinterpret_cast<float4*>(smem + OFF_WARC1)[k * 32 + l] = w4;
        smem[OFF_WC2R + k * 64 + 2 * l]     = __fadd_rn(Wcin[l * 128 + 64 + k],        Wcrec[l * 64 + k]);
        smem[OFF_WC2R + k * 64 + 2 * l + 1] = __fadd_rn(Wcin[(l + 32) * 128 + 64 + k], Wcrec[(l + 32) * 64 + k]);
    }
    __syncthreads();

    const int lane = tid & 31;
    const float4* wsain  = reinterpret_cast<const float4*>(smem + OFF_WSAIN)  + lane;
    const float4* wsrec4 = reinterpret_cast<const float4*>(smem + OFF_WSREC4) + lane;
    const float4* warc1  = reinterpret_cast<const float4*>(smem + OFF_WARC1)  + lane;
    const float2* wc2r   = reinterpret_cast<const float2*>(smem + OFF_WC2R)   + lane;

    unsigned b = blockIdx.x * (unsigned)WPB + (unsigned)(tid >> 5);

    while (b < (unsigned)Bsz) {
        const float* srow = state  + (size_t)b * Sdim;
        const float* arow = action + (size_t)b * Adim;

        float c0, c1;
        if (lane < 24) c0 = fmaxf(__fmul_rn(50.f, srow[lane]), 0.f);
        else           c0 = fmaxf(__fmul_rn(-50.f, srow[lane - 24]), 0.f);
        if (lane < 16)      c1 = fmaxf(__fmul_rn(-50.f, srow[8 + lane]), 0.f);
        else if (lane < 20) c1 = fmaxf(__fmul_rn(50.f, arow[lane - 16]), 0.f);
        else if (lane < 24) c1 = fmaxf(__fmul_rn(-50.f, arow[lane - 20]), 0.f);
        else                c1 = 0.f;

        bool alw0 = __fmul_rn(0.1f, c0) > 1.0f;
        bool alw1 = (lane < 24) && (__fmul_rn(0.1f, c1) > 1.0f);
        unsigned alo = __ballot_sync(FULLM, alw0);
        unsigned ahi = __ballot_sync(FULLM, alw1);
        unsigned long long x_always = (unsigned long long)alo | ((unsigned long long)ahi << 32);

        // hoisted base sums over always-on inputs
        float bs0 = 0.f, bs1 = 0.f, ba0 = 0.f, ba1 = 0.f;
        {
            unsigned m = (unsigned)x_always;
            while (m) { int k = __ffs(m) - 1; m &= m - 1;
                        float4 w = wsain[k * 32];
                        bs0 += w.x; bs1 += w.y; ba0 += w.z; ba1 += w.w; }
            m = (unsigned)(x_always >> 32);
            while (m) { int k = __ffs(m) - 1 + 32; m &= m - 1;
                        float4 w = wsain[k * 32];
                        bs0 += w.x; bs1 += w.y; ba0 += w.z; ba1 += w.w; }
        }

        float ve0 = 0.f, ve1 = 0.f;
        float v0 = 0.f, v1 = 0.f;
        float i0 = 0.f, i1 = 0.f;
        float r0 = 0.f, r1 = 0.f;           // z_prev @ Wsrec (carried)
        float vli = 0.f, ili = 0.f;
        float vmax = -3.0e38f;

        for (int t = 0; t < Tlen; t++) {
            // ---- encoder (FMA-contracted like XLA) ----
            ve0 = __fmaf_rn(0.1f, __fsub_rn(c0, ve0), ve0);
            bool s0 = __fsub_rn(ve0, 1.0f) > 0.0f; if (s0) ve0 = 0.f;
            ve1 = __fmaf_rn(0.1f, __fsub_rn(c1, ve1), ve1);
            bool s1 = (lane < 24) && (__fsub_rn(ve1, 1.0f) > 0.0f); if (s1) ve1 = 0.f;
            unsigned mlo = __ballot_sync(FULLM, s0);
            unsigned mhi = __ballot_sync(FULLM, s1);
            unsigned long long xall = (unsigned long long)mlo | ((unsigned long long)mhi << 32);

            // ---- lif1 ----
            float id0 = __fmaf_rn(-0.2f, i0, i0);
            float id1 = __fmaf_rn(-0.2f, i1, i1);
            float vd0 = __fmaf_rn(0.1f, __fsub_rn(i0, v0), v0);
            float vd1 = __fmaf_rn(0.1f, __fsub_rn(i1, v1), v1);
            bool zs0 = __fsub_rn(vd0, 1.0f) > 0.0f; v0 = zs0 ? 0.f : vd0;
            bool zs1 = __fsub_rn(vd1, 1.0f) > 0.0f; v1 = zs1 ? 0.f : vd1;

            float a0 = bs0, a1 = bs1, p0 = ba0, p1 = ba1;
            unsigned long long dev = xall & ~x_always;
            {
                unsigned m = (unsigned)dev;
                while (m) { int k = __ffs(m) - 1; m &= m - 1;
                            float4 w = wsain[k * 32];
                            a0 = __fadd_rn(a0, w.x); a1 = __fadd_rn(a1, w.y);
                            p0 = __fadd_rn(p0, w.z); p1 = __fadd_rn(p1, w.w); }
                m = (unsigned)(dev >> 32);
                while (m) { int k = __ffs(m) - 1 + 32; m &= m - 1;
                            float4 w = wsain[k * 32];
                            a0 = __fadd_rn(a0, w.x); a1 = __fadd_rn(a1, w.y);
                            p0 = __fadd_rn(p0, w.z); p1 = __fadd_rn(p1, w.w); }
            }
            i0 = __fadd_rn(__fadd_rn(id0, a0), r0);
            i1 = __fadd_rn(__fadd_rn(id1, a1), r1);

            unsigned zslo = __ballot_sync(FULLM, zs0);
            unsigned zshi = __ballot_sync(FULLM, zs1);
            unsigned long long zsm = (unsigned long long)zslo | ((unsigned long long)zshi << 32);

            // ---- lif2 (+ Wcin[:, :64]·z_s for lif3) ----
            id0 = __fmaf_rn(-0.2f, i0, i0);
            id1 = __fmaf_rn(-0.2f, i1, i1);
            vd0 = __fmaf_rn(0.1f, __fsub_rn(i0, v0), v0);
            vd1 = __fmaf_rn(0.1f, __fsub_rn(i1, v1), v1);
            bool za0 = __fsub_rn(vd0, 1.0f) > 0.0f; v0 = za0 ? 0.f : vd0;
            bool za1 = __fsub_rn(vd1, 1.0f) > 0.0f; v1 = za1 ? 0.f : vd1;

            float q0 = 0.f, q1 = 0.f, u0 = 0.f, u1 = 0.f;
            {
                unsigned m = (unsigned)zsm;
                while (m) { int k = __ffs(m) - 1; m &= m - 1;
                            float4 w = warc1[k * 32];
                            q0 = __fadd_rn(q0, w.x); q1 = __fadd_rn(q1, w.y);
                            u0 = __fadd_rn(u0, w.z); u1 = __fadd_rn(u1, w.w); }
                m = (unsigned)(zsm >> 32);
                while (m) { int k = __ffs(m) - 1 + 32; m &= m - 1;
                            float4 w = warc1[k * 32];
                            q0 = __fadd_rn(q0, w.x); q1 = __fadd_rn(q1, w.y);
                            u0 = __fadd_rn(u0, w.z); u1 = __fadd_rn(u1, w.w); }
            }
            i0 = __fadd_rn(__fadd_rn(id0, p0), q0);
            i1 = __fadd_rn(__fadd_rn(id1, p1), q1);

            unsigned zalo = __ballot_sync(FULLM, za0);
            unsigned zahi = __ballot_sync(FULLM, za1);
            unsigned long long zam = (unsigned long long)zalo | ((unsigned long long)zahi << 32);

            // ---- lif3 (merged Wcin2+Wcrec on z_a) ----
            id0 = __fmaf_rn(-0.2f, i0, i0);
            id1 = __fmaf_rn(-0.2f, i1, i1);
            vd0 = __fmaf_rn(0.1f, __fsub_rn(i0, v0), v0);
            vd1 = __fmaf_rn(0.1f, __fsub_rn(i1, v1), v1);
            bool z0 = __fsub_rn(vd0, 1.0f) > 0.0f; v0 = z0 ? 0.f : vd0;
            bool z1 = __fsub_rn(vd1, 1.0f) > 0.0f; v1 = z1 ? 0.f : vd1;

            float e0 = u0, e1 = u1;
            {
                unsigned m = (unsigned)zam;
                while (m) { int k = __ffs(m) - 1; m &= m - 1;
                            float2 w = wc2r[k * 32];
                            e0 = __fadd_rn(e0, w.x); e1 = __fadd_rn(e1, w.y); }
                m = (unsigned)(zam >> 32);
                while (m) { int k = __ffs(m) - 1 + 32; m &= m - 1;
                            float2 w = wc2r[k * 32];
                            e0 = __fadd_rn(e0, w.x); e1 = __fadd_rn(e1, w.y); }
            }
            i0 = __fadd_rn(id0, e0);
            i1 = __fadd_rn(id1, e1);

            unsigned zlo = __ballot_sync(FULLM, z0);
            unsigned zhi = __ballot_sync(FULLM, z1);
            unsigned long long zm = (unsigned long long)zlo | ((unsigned long long)zhi << 32);

            // ---- combined recurrent+readout gather over fresh zm ----
            float nr0 = 0.f, nr1 = 0.f, ro = 0.f;
            {
                unsigned m = (unsigned)zm;
                while (m) { int k = __ffs(m) - 1; m &= m - 1;
                            float4 w = wsrec4[k * 32];
                            nr0 = __fadd_rn(nr0, w.x); nr1 = __fadd_rn(nr1, w.y);
                            ro  = __fadd_rn(ro,  w.z); }
                m = (unsigned)(zm >> 32);
                while (m) { int k = __ffs(m) - 1 + 32; m &= m - 1;
                            float4 w = wsrec4[k * 32];
                            nr0 = __fadd_rn(nr0, w.x); nr1 = __fadd_rn(nr1, w.y);
                            ro  = __fadd_rn(ro,  w.z); }
            }
            r0 = nr0; r1 = nr1;

            // ---- LI readout ----
            vli = __fmaf_rn(0.1f, __fsub_rn(ili, vli), vli);
            ili = __fadd_rn(__fmaf_rn(-0.2f, ili, ili), ro);
            vmax = fmaxf(vmax, vli);
        }

        if (lane == 0) out[b] = vmax;

        if (lane == 0) b = atomicAdd(&g_ticket, 1u);
        b = __shfl_sync(FULLM, b, 0);
    }
}

extern "C" void kernel_launch(void* const* d_in, const int* in_sizes, int n_in,
                              void* d_out, int out_size)
{
    const float* state  = (const float*)d_in[0];
    const float* action = (const float*)d_in[1];
    const float* Wsin   = (const float*)d_in[2];
    const float* Wsrec  = (const float*)d_in[3];
    const float* Wain   = (const float*)d_in[4];
    const float* Warec  = (const float*)d_in[5];
    const float* Wcin   = (const float*)d_in[6];
    const float* Wcrec  = (const float*)d_in[7];
    const float* Wro    = (const float*)d_in[8];

    int sms = 148;
    cudaDeviceGetAttribute(&sms, cudaDevAttrMultiProcessorCount, 0);
    int grid = sms * 2;                       // 2 CTAs/SM (smem allows exactly 2 table copies)
    unsigned nwarps = (unsigned)grid * (unsigned)WPB;

    cudaFuncSetAttribute(snn_kernel, cudaFuncAttributeMaxDynamicSharedMemorySize,
                         SMEM_FLOATS * sizeof(float));

    reset_ticket_kernel<<<1, 1>>>(nwarps);
    snn_kernel<<<grid, THREADS, SMEM_FLOATS * sizeof(float)>>>(
        state, action, Wsin, Wsrec, Wain, Warec, Wcin, Wcrec, Wro, (float*)d_out);
}